// round 16
// baseline (speedup 1.0000x reference)
#include <cuda_runtime.h>
#include <cuda_bf16.h>
#include <cstdint>
#include <math.h>

// ---------------------------------------------------------------------------
// Problem constants
// ---------------------------------------------------------------------------
#define NB_C   100000
#define DIM    64
#define BATCH  1024
#define BM     64                   // samples per CTA tile
#define BN     128                  // classes per CTA tile
#define NT     782                  // ceil(100000/128)
#define MT     16                   // 1024/64
#define CPAD   (NT * BN)            // 100096; pad classes contribute exp(-1)
#define NBLK   (NT * MT)            // 12512 one-shot CTAs (mt fastest)
#define PITCH  72                   // smem row pitch in bf16 (144 B)
#define ROWB   (PITCH * 2)

#define LOG2E  1.4426950408889634f
#define LN2    0.69314718055994531f

#define NORM_BLOCKS (CPAD / 8)      // 12512 (8 warps/block, 1 row/warp)
#define PREP_BLOCKS 32
#define K1_GRID (NORM_BLOCKS + PREP_BLOCKS + 1)

// smem layout for gemm (bytes)
#define OFF_A 0
#define OFF_B (BM * ROWB)           // 9216
#define SMEM_BYTES (OFF_B + BN * ROWB)   // 27648 -> 3+ CTAs/SM by smem

// ---------------------------------------------------------------------------
// Device scratch
// ---------------------------------------------------------------------------
__device__ __align__(256) __nv_bfloat16 g_Xb[BATCH * DIM];   // bf16(xs)
__device__ __align__(256) __nv_bfloat16 g_Pb[CPAD * DIM];    // bf16(2*log2e*p/||p||)
__device__ float    g_S[BATCH];     // S_i = sum_c exp(t_ic - 1) (incl. 96 pad)
__device__ unsigned g_cnt;          // gemm completion ticket

// ---------------------------------------------------------------------------
// PTX helpers (sm_80-generic: ldmatrix / mma.sync / cp.async — legal on sm_103)
// ---------------------------------------------------------------------------
__device__ __forceinline__ uint32_t smem_u32(const void* p) {
    uint32_t a;
    asm("{ .reg .u64 t; cvta.to.shared.u64 t, %1; cvt.u32.u64 %0, t; }"
        : "=r"(a) : "l"(p));
    return a;
}
__device__ __forceinline__ void ldsm4(uint32_t* r, uint32_t addr) {
    asm volatile("ldmatrix.sync.aligned.m8n8.x4.shared.b16 {%0,%1,%2,%3}, [%4];"
        : "=r"(r[0]), "=r"(r[1]), "=r"(r[2]), "=r"(r[3]) : "r"(addr));
}
__device__ __forceinline__ void mma_bf16(float* c, const uint32_t* a,
                                         uint32_t b0, uint32_t b1) {
    asm volatile(
        "mma.sync.aligned.m16n8k16.row.col.f32.bf16.bf16.f32 "
        "{%0,%1,%2,%3}, {%4,%5,%6,%7}, {%8,%9}, {%0,%1,%2,%3};"
        : "+f"(c[0]), "+f"(c[1]), "+f"(c[2]), "+f"(c[3])
        : "r"(a[0]), "r"(a[1]), "r"(a[2]), "r"(a[3]), "r"(b0), "r"(b1));
}
__device__ __forceinline__ void mma_bf16_z(float* c, const uint32_t* a,
                                           uint32_t b0, uint32_t b1) {
    asm volatile(
        "mma.sync.aligned.m16n8k16.row.col.f32.bf16.bf16.f32 "
        "{%0,%1,%2,%3}, {%4,%5,%6,%7}, {%8,%9}, {%10,%11,%12,%13};"
        : "=f"(c[0]), "=f"(c[1]), "=f"(c[2]), "=f"(c[3])
        : "r"(a[0]), "r"(a[1]), "r"(a[2]), "r"(a[3]), "r"(b0), "r"(b1),
          "f"(0.0f), "f"(0.0f), "f"(0.0f), "f"(0.0f));
}
__device__ __forceinline__ void cpasync16(uint32_t dst, const void* src) {
    asm volatile("cp.async.cg.shared.global [%0], [%1], 16;" :: "r"(dst), "l"(src));
}
#define CP_COMMIT() asm volatile("cp.async.commit_group;")
#define CP_WAIT0()  asm volatile("cp.async.wait_group 0;")

__device__ __forceinline__ float ex2(float x) {       // bare MUFU.EX2
    float r;
    asm("ex2.approx.f32 %0, %1;" : "=f"(r) : "f"(x));
    return r;
}

// ---------------------------------------------------------------------------
// K1: (a) normalize proxies (2*log2e folded) -> bf16 g_Pb, 1 warp/row;
//     (b) xs -> bf16 g_Xb; (c) zero g_S / g_cnt. One launch.
// ---------------------------------------------------------------------------
__global__ void prep_kernel(const float* __restrict__ proxies,
                            const float* __restrict__ xs) {
    const int b = blockIdx.x, tid = threadIdx.x, wid = tid >> 5, lane = tid & 31;

    if (b < NORM_BLOCKS) {
        int row = b * 8 + wid;                   // < CPAD by construction
        float2 v = make_float2(0.f, 0.f);
        if (row < NB_C) v = reinterpret_cast<const float2*>(proxies)[(size_t)row * 32 + lane];
        float ss = v.x * v.x + v.y * v.y;
        #pragma unroll
        for (int off = 16; off >= 1; off >>= 1)
            ss += __shfl_xor_sync(0xffffffffu, ss, off);
        float sc = (2.0f * LOG2E) / fmaxf(sqrtf(ss), 1e-12f);
        __nv_bfloat162 o;
        o.x = __float2bfloat16(v.x * sc);        // pad rows: exact zeros
        o.y = __float2bfloat16(v.y * sc);
        reinterpret_cast<__nv_bfloat162*>(g_Pb)[(size_t)row * 32 + lane] = o;
    } else if (b < NORM_BLOCKS + PREP_BLOCKS) {
        int g = (b - NORM_BLOCKS) * 2048 + tid * 8;      // 8 floats/thread
        float4 v0 = reinterpret_cast<const float4*>(xs)[g / 4];
        float4 v1 = reinterpret_cast<const float4*>(xs)[g / 4 + 1];
        __nv_bfloat16 o[8] = {
            __float2bfloat16(v0.x), __float2bfloat16(v0.y),
            __float2bfloat16(v0.z), __float2bfloat16(v0.w),
            __float2bfloat16(v1.x), __float2bfloat16(v1.y),
            __float2bfloat16(v1.z), __float2bfloat16(v1.w) };
        *reinterpret_cast<uint4*>(&g_Xb[g]) = *reinterpret_cast<uint4*>(o);
    } else {
        #pragma unroll
        for (int k = 0; k < 4; ++k) g_S[tid * 4 + k] = 0.0f;
        if (tid == 0) g_cnt = 0u;
    }
}

// ---------------------------------------------------------------------------
// K2: one-shot GEMM CTAs (64x128, K=64, bf16) + fused exp2/row-sum epilogue.
// 3 CTAs/SM. Last-finishing CTA computes the final loss.
// ---------------------------------------------------------------------------
__global__ void __launch_bounds__(256, 3) gemm_kernel(const float* __restrict__ proxies,
                                                      const float* __restrict__ xs,
                                                      const int*   __restrict__ ysw,
                                                      float*       __restrict__ out) {
    extern __shared__ __align__(16) char sm[];
    __shared__ float rsum[BM];
    __shared__ unsigned s_ticket;
    const uint32_t sb = smem_u32(sm);
    const int tid = threadIdx.x, wid = tid >> 5, lane = tid & 31;
    const int mt = blockIdx.x & 15, nt = blockIdx.x >> 4;   // mt fastest: B L2 reuse

    // -- async tile loads: A 64x128B, B 128x128B (bf16 row-major)
    {
        const char* srcA = (const char*)(g_Xb + (size_t)mt * BM * DIM);
        const char* srcB = (const char*)(g_Pb + (size_t)nt * BN * DIM);
        #pragma unroll
        for (int it = 0; it < 2; ++it) {                   // A: 512 chunks
            int g = tid + it * 256;
            uint32_t doff = (uint32_t)(g >> 3) * ROWB + (g & 7) * 16;
            cpasync16(sb + OFF_A + doff, srcA + (size_t)g * 16);
        }
        #pragma unroll
        for (int it = 0; it < 4; ++it) {                   // B: 1024 chunks
            int g = tid + it * 256;
            uint32_t doff = (uint32_t)(g >> 3) * ROWB + (g & 7) * 16;
            cpasync16(sb + OFF_B + doff, srcB + (size_t)g * 16);
        }
        CP_COMMIT();
    }
    if (tid < BM) rsum[tid] = 0.0f;

    const int wm = (wid & 1) * 32;                         // 2 warps along M
    const int wn = (wid >> 1) * 32;                        // 4 warps along N
    const int r  = lane & 7, q = lane >> 3, gq = lane >> 2;
    const uint32_t aOff = (uint32_t)(wm + r + (q & 1) * 8) * ROWB + (q >> 1) * 16;
    const uint32_t bOff = (uint32_t)(wn + r + (q >> 1) * 8) * ROWB + (q & 1) * 16;

    CP_WAIT0();
    __syncthreads();

    float acc[2][4][4];
    #pragma unroll
    for (int ks = 0; ks < 4; ++ks) {
        const uint32_t kb = ks * 32;
        uint32_t a[2][4];
        #pragma unroll
        for (int mb = 0; mb < 2; ++mb)
            ldsm4(a[mb], sb + OFF_A + aOff + mb * 16 * ROWB + kb);
        #pragma unroll
        for (int np = 0; np < 2; ++np) {
            uint32_t bfr[4];
            ldsm4(bfr, sb + OFF_B + bOff + np * 16 * ROWB + kb);
            #pragma unroll
            for (int h = 0; h < 2; ++h)
                #pragma unroll
                for (int mb = 0; mb < 2; ++mb) {
                    if (ks == 0)
                        mma_bf16_z(acc[mb][np * 2 + h], a[mb], bfr[h * 2], bfr[h * 2 + 1]);
                    else
                        mma_bf16(acc[mb][np * 2 + h], a[mb], bfr[h * 2], bfr[h * 2 + 1]);
                }
        }
    }

    // -- fused epilogue: exp2(t' - log2e) = exp(t-1); quad-reduce; smem stage
    #pragma unroll
    for (int mb = 0; mb < 2; ++mb) {
        float sA = 0.f, sB = 0.f;
        #pragma unroll
        for (int nb = 0; nb < 4; ++nb) {
            sA += ex2(acc[mb][nb][0] - LOG2E) + ex2(acc[mb][nb][1] - LOG2E);
            sB += ex2(acc[mb][nb][2] - LOG2E) + ex2(acc[mb][nb][3] - LOG2E);
        }
        sA += __shfl_xor_sync(0xffffffffu, sA, 1);
        sA += __shfl_xor_sync(0xffffffffu, sA, 2);
        sB += __shfl_xor_sync(0xffffffffu, sB, 1);
        sB += __shfl_xor_sync(0xffffffffu, sB, 2);
        if ((lane & 3) == 0) {
            int lrow = wm + mb * 16 + gq;
            atomicAdd(&rsum[lrow],     sA);
            atomicAdd(&rsum[lrow + 8], sB);
        }
    }
    __syncthreads();
    if (tid < BM) atomicAdd(&g_S[mt * BM + tid], rsum[tid]);

    // -- ticket: last-finishing CTA computes the loss
    __threadfence();
    if (tid == 0) s_ticket = atomicAdd(&g_cnt, 1u);
    __syncthreads();
    if (s_ticket != NBLK - 1) return;

    // ---- final: 1024 samples, 8 threads/sample, mirrors the bf16 product ----
    bool is64 = true;
    #pragma unroll
    for (int j = 1; j < 16; j += 2)
        if (ysw[j] != 0) is64 = false;               // int64 labels: odd words 0

    const int l8 = tid & 7, sg = tid >> 3;
    float lsum = 0.f;
    for (int k = 0; k < 32; ++k) {
        int s = k * 32 + sg;
        int y = is64 ? ysw[2 * s] : ysw[s];
        const float4* pv = reinterpret_cast<const float4*>(proxies + (size_t)y * DIM + l8 * 8);
        const float4* xv = reinterpret_cast<const float4*>(xs      + (size_t)s * DIM + l8 * 8);
        float4 p0 = pv[0], p1 = pv[1];
        float4 x0 = xv[0], x1 = xv[1];
        float ss = p0.x*p0.x + p0.y*p0.y + p0.z*p0.z + p0.w*p0.w
                 + p1.x*p1.x + p1.y*p1.y + p1.z*p1.z + p1.w*p1.w;
        ss += __shfl_xor_sync(0xffffffffu, ss, 1);
        ss += __shfl_xor_sync(0xffffffffu, ss, 2);
        ss += __shfl_xor_sync(0xffffffffu, ss, 4);
        float sc = (2.0f * LOG2E) / fmaxf(sqrtf(ss), 1e-12f);
        float pe[8] = {p0.x, p0.y, p0.z, p0.w, p1.x, p1.y, p1.z, p1.w};
        float xe[8] = {x0.x, x0.y, x0.z, x0.w, x1.x, x1.y, x1.z, x1.w};
        float dot = 0.f;
        #pragma unroll
        for (int e = 0; e < 8; ++e) {
            float pb = __bfloat162float(__float2bfloat16(pe[e] * sc));
            float xb = __bfloat162float(__float2bfloat16(xe[e]));
            dot += pb * xb;
        }
        dot += __shfl_xor_sync(0xffffffffu, dot, 1);
        dot += __shfl_xor_sync(0xffffffffu, dot, 2);
        dot += __shfl_xor_sync(0xffffffffu, dot, 4);
        if (l8 == 0) {
            // dot = t' = log2e * t_pos;  e^{t_pos-1} = 2^{t' - log2e}
            float S = g_S[s] - (float)(CPAD - NB_C) * expf(-1.0f);  // remove pads
            float tpos = dot * LN2 - 1.0f;                          // natural units
            lsum += logf(S - ex2(dot - LOG2E)) - tpos;
        }
    }
    __shared__ float red[256];
    red[tid] = lsum;                                  // nonzero only for l8==0
    __syncthreads();
    for (int sft = 128; sft > 0; sft >>= 1) {
        if (tid < sft) red[tid] += red[tid + sft];
        __syncthreads();
    }
    if (tid == 0) out[0] = red[0] * (1.0f / 1024.0f);
}

// ---------------------------------------------------------------------------
// Launch: 2 kernels, graph-capturable.
// ---------------------------------------------------------------------------
extern "C" void kernel_launch(void* const* d_in, const int* in_sizes, int n_in,
                              void* d_out, int out_size) {
    const float* xs = nullptr; const int* ys = nullptr; const float* proxies = nullptr;
    for (int i = 0; i < n_in; ++i) {
        if      (in_sizes[i] == BATCH * DIM) xs      = (const float*)d_in[i];
        else if (in_sizes[i] == BATCH)       ys      = (const int*)d_in[i];
        else if (in_sizes[i] == NB_C * DIM)  proxies = (const float*)d_in[i];
    }
    (void)out_size;

    cudaFuncSetAttribute(gemm_kernel, cudaFuncAttributeMaxDynamicSharedMemorySize,
                         SMEM_BYTES);

    prep_kernel<<<K1_GRID, 256>>>(proxies, xs);
    gemm_kernel<<<NBLK, 256, SMEM_BYTES>>>(proxies, xs, ys, (float*)d_out);
}

// round 17
// speedup vs baseline: 1.5270x; 1.5270x over previous
#include <cuda_runtime.h>
#include <cuda_bf16.h>
#include <cstdint>
#include <math.h>

// ---------------------------------------------------------------------------
// Problem constants
// ---------------------------------------------------------------------------
#define NB_C   100000
#define DIM    64
#define BATCH  1024
#define BM     128                  // samples per tile (fixed per CTA)
#define BN     128                  // classes per tile (streamed)
#define NT     782                  // ceil(100000/128)
#define CPAD   (NT * BN)            // 100096; pad classes contribute exp(-1)
#define PITCH  72                   // smem row pitch in bf16 (144 B)
#define ROWB   (PITCH * 2)

#define GRID   296                  // persistent: 2 CTAs/SM x 148
#define MTG    8                    // mt groups
#define CPM    (GRID / MTG)         // 37 CTAs per mt group

#define LOG2E  1.4426950408889634f
#define LN2    0.69314718055994531f

#define NORM_BLOCKS (CPAD / 8)      // 12512
#define PREP_BLOCKS 32
#define K1_GRID (NORM_BLOCKS + PREP_BLOCKS + 1)

// smem layout (bytes): A tile + 2x B tile
#define OFF_A 0
#define OFF_B (BM * ROWB)                       // 18432
#define B_SZ  (BN * ROWB)                       // 18432
#define SMEM_BYTES (OFF_B + 2 * B_SZ)           // 55296

// ---------------------------------------------------------------------------
// Device scratch
// ---------------------------------------------------------------------------
__device__ __align__(256) __nv_bfloat16 g_Xb[BATCH * DIM];   // bf16(xs)
__device__ __align__(256) __nv_bfloat16 g_Pb[CPAD * DIM];    // bf16(2*log2e*p/||p||)
__device__ float    g_S[BATCH];     // S_i (base-2 folded), incl. 96 pad classes
__device__ unsigned g_cnt;          // completion ticket

// ---------------------------------------------------------------------------
// PTX helpers (sm_80-generic: ldmatrix / mma.sync / cp.async — legal on sm_103)
// ---------------------------------------------------------------------------
__device__ __forceinline__ uint32_t smem_u32(const void* p) {
    uint32_t a;
    asm("{ .reg .u64 t; cvta.to.shared.u64 t, %1; cvt.u32.u64 %0, t; }"
        : "=r"(a) : "l"(p));
    return a;
}
__device__ __forceinline__ void ldsm4(uint32_t* r, uint32_t addr) {
    asm volatile("ldmatrix.sync.aligned.m8n8.x4.shared.b16 {%0,%1,%2,%3}, [%4];"
        : "=r"(r[0]), "=r"(r[1]), "=r"(r[2]), "=r"(r[3]) : "r"(addr));
}
__device__ __forceinline__ void mma_bf16(float* c, const uint32_t* a,
                                         uint32_t b0, uint32_t b1) {
    asm volatile(
        "mma.sync.aligned.m16n8k16.row.col.f32.bf16.bf16.f32 "
        "{%0,%1,%2,%3}, {%4,%5,%6,%7}, {%8,%9}, {%0,%1,%2,%3};"
        : "+f"(c[0]), "+f"(c[1]), "+f"(c[2]), "+f"(c[3])
        : "r"(a[0]), "r"(a[1]), "r"(a[2]), "r"(a[3]), "r"(b0), "r"(b1));
}
__device__ __forceinline__ void mma_bf16_z(float* c, const uint32_t* a,
                                           uint32_t b0, uint32_t b1) {
    asm volatile(
        "mma.sync.aligned.m16n8k16.row.col.f32.bf16.bf16.f32 "
        "{%0,%1,%2,%3}, {%4,%5,%6,%7}, {%8,%9}, {%10,%11,%12,%13};"
        : "=f"(c[0]), "=f"(c[1]), "=f"(c[2]), "=f"(c[3])
        : "r"(a[0]), "r"(a[1]), "r"(a[2]), "r"(a[3]), "r"(b0), "r"(b1),
          "f"(0.0f), "f"(0.0f), "f"(0.0f), "f"(0.0f));
}
__device__ __forceinline__ void cpasync16(uint32_t dst, const void* src) {
    asm volatile("cp.async.cg.shared.global [%0], [%1], 16;" :: "r"(dst), "l"(src));
}
#define CP_COMMIT() asm volatile("cp.async.commit_group;")
#define CP_WAIT1()  asm volatile("cp.async.wait_group 1;")
#define CP_WAIT0()  asm volatile("cp.async.wait_group 0;")

__device__ __forceinline__ float ex2(float x) {       // bare MUFU.EX2
    float r;
    asm("ex2.approx.f32 %0, %1;" : "=f"(r) : "f"(x));
    return r;
}

// ---------------------------------------------------------------------------
// K1: normalize proxies (2*log2e folded) -> bf16 g_Pb; xs -> bf16 g_Xb;
//     zero g_S / g_cnt. One launch.
// ---------------------------------------------------------------------------
__global__ void prep_kernel(const float* __restrict__ proxies,
                            const float* __restrict__ xs) {
    const int b = blockIdx.x, tid = threadIdx.x, wid = tid >> 5, lane = tid & 31;

    if (b < NORM_BLOCKS) {
        int row = b * 8 + wid;
        float2 v = make_float2(0.f, 0.f);
        if (row < NB_C) v = reinterpret_cast<const float2*>(proxies)[(size_t)row * 32 + lane];
        float ss = v.x * v.x + v.y * v.y;
        #pragma unroll
        for (int off = 16; off >= 1; off >>= 1)
            ss += __shfl_xor_sync(0xffffffffu, ss, off);
        float sc = (2.0f * LOG2E) / fmaxf(sqrtf(ss), 1e-12f);
        __nv_bfloat162 o;
        o.x = __float2bfloat16(v.x * sc);            // pad rows: exact zeros
        o.y = __float2bfloat16(v.y * sc);
        reinterpret_cast<__nv_bfloat162*>(g_Pb)[(size_t)row * 32 + lane] = o;
    } else if (b < NORM_BLOCKS + PREP_BLOCKS) {
        int g = (b - NORM_BLOCKS) * 2048 + tid * 8;
        float4 v0 = reinterpret_cast<const float4*>(xs)[g / 4];
        float4 v1 = reinterpret_cast<const float4*>(xs)[g / 4 + 1];
        __nv_bfloat16 o[8] = {
            __float2bfloat16(v0.x), __float2bfloat16(v0.y),
            __float2bfloat16(v0.z), __float2bfloat16(v0.w),
            __float2bfloat16(v1.x), __float2bfloat16(v1.y),
            __float2bfloat16(v1.z), __float2bfloat16(v1.w) };
        *reinterpret_cast<uint4*>(&g_Xb[g]) = *reinterpret_cast<uint4*>(o);
    } else {
        #pragma unroll
        for (int k = 0; k < 4; ++k) g_S[tid * 4 + k] = 0.0f;
        if (tid == 0) g_cnt = 0u;
    }
}

// ---------------------------------------------------------------------------
// K2: persistent pipelined GEMM. CTA = fixed mt + streamed nt range.
// A resident; B double-buffered cp.async. Row sums accumulate in registers
// across the whole chunk; one flush at end. Last CTA computes the loss.
// ---------------------------------------------------------------------------
__device__ __forceinline__ void prefetch_B(int nt, int buf, uint32_t sb, int tid) {
    const char* src = (const char*)(g_Pb + (size_t)nt * BN * DIM);
    const uint32_t bb = sb + OFF_B + (uint32_t)buf * B_SZ;
    #pragma unroll
    for (int it = 0; it < 4; ++it) {                 // 1024 16B chunks
        int g = tid + it * 256;
        uint32_t doff = (uint32_t)(g >> 3) * ROWB + (g & 7) * 16;
        cpasync16(bb + doff, src + (size_t)g * 16);
    }
    CP_COMMIT();
}

__global__ void __launch_bounds__(256, 2) gemm_kernel(const float* __restrict__ proxies,
                                                      const float* __restrict__ xs,
                                                      const int*   __restrict__ ysw,
                                                      float*       __restrict__ out) {
    extern __shared__ __align__(16) char sm[];
    __shared__ unsigned s_ticket;
    const uint32_t sb = smem_u32(sm);
    const int tid = threadIdx.x, wid = tid >> 5, lane = tid & 31;

    const int mt  = blockIdx.x & 7;                  // fixed m-tile
    const int cid = blockIdx.x >> 3;                 // 0..36 within mt group
    const int per = NT / CPM, rem = NT % CPM;        // 21, 5
    const int n0  = cid * per + (cid < rem ? cid : rem);
    const int cnt = per + (cid < rem ? 1 : 0);

    // A tile (group 0) then B(n0) (group 1)
    {
        const char* srcA = (const char*)(g_Xb + (size_t)mt * BM * DIM);
        #pragma unroll
        for (int it = 0; it < 4; ++it) {
            int g = tid + it * 256;
            uint32_t doff = (uint32_t)(g >> 3) * ROWB + (g & 7) * 16;
            cpasync16(sb + OFF_A + doff, srcA + (size_t)g * 16);
        }
        CP_COMMIT();
    }
    prefetch_B(n0, 0, sb, tid);

    const int wm = (wid & 3) * 32;                   // 4 warps along M
    const int wn = (wid >> 2) * 64;                  // 2 warps along N
    const int r  = lane & 7, q = lane >> 3, gq = lane >> 2;
    const uint32_t aOff = (uint32_t)(wm + r + (q & 1) * 8) * ROWB + (q >> 1) * 16;
    const uint32_t bOff = (uint32_t)(wn + r + (q >> 1) * 8) * ROWB + (q & 1) * 16;

    float rs[2][2] = {{0.f, 0.f}, {0.f, 0.f}};       // chunk-long row sums

    for (int j = 0; j < cnt; ++j) {
        if (j + 1 < cnt) { prefetch_B(n0 + j + 1, (j + 1) & 1, sb, tid); CP_WAIT1(); }
        else             { CP_WAIT0(); }
        __syncthreads();                             // B(j) (+A on j=0) visible

        const uint32_t bbase = sb + OFF_B + (uint32_t)(j & 1) * B_SZ;
        float acc[2][8][4];
        #pragma unroll
        for (int ks = 0; ks < 4; ++ks) {
            const uint32_t kb = ks * 32;
            uint32_t a[2][4];
            #pragma unroll
            for (int mb = 0; mb < 2; ++mb)
                ldsm4(a[mb], sb + OFF_A + aOff + mb * 16 * ROWB + kb);
            #pragma unroll
            for (int np = 0; np < 4; ++np) {
                uint32_t bfr[4];
                ldsm4(bfr, bbase + bOff + np * 16 * ROWB + kb);
                #pragma unroll
                for (int h = 0; h < 2; ++h)
                    #pragma unroll
                    for (int mb = 0; mb < 2; ++mb) {
                        if (ks == 0)
                            mma_bf16_z(acc[mb][np * 2 + h], a[mb], bfr[h * 2], bfr[h * 2 + 1]);
                        else
                            mma_bf16(acc[mb][np * 2 + h], a[mb], bfr[h * 2], bfr[h * 2 + 1]);
                    }
            }
        }

        // epilogue: 2^(t' - log2e) = exp(t-1); accumulate into registers only
        #pragma unroll
        for (int mb = 0; mb < 2; ++mb) {
            #pragma unroll
            for (int nb = 0; nb < 8; ++nb) {
                rs[mb][0] += ex2(acc[mb][nb][0] - LOG2E) + ex2(acc[mb][nb][1] - LOG2E);
                rs[mb][1] += ex2(acc[mb][nb][2] - LOG2E) + ex2(acc[mb][nb][3] - LOG2E);
            }
        }
        __syncthreads();   // all reads of B(j) done before j+2's prefetch lands
    }

    // flush chunk row sums: quad-reduce then one atomic per row per warp
    #pragma unroll
    for (int mb = 0; mb < 2; ++mb) {
        #pragma unroll
        for (int e = 0; e < 2; ++e) {
            float s = rs[mb][e];
            s += __shfl_xor_sync(0xffffffffu, s, 1);
            s += __shfl_xor_sync(0xffffffffu, s, 2);
            if ((lane & 3) == 0)
                atomicAdd(&g_S[mt * BM + wm + mb * 16 + gq + e * 8], s);
        }
    }

    // ticket: last-finishing CTA computes the loss
    __threadfence();
    if (tid == 0) s_ticket = atomicAdd(&g_cnt, 1u);
    __syncthreads();
    if (s_ticket != GRID - 1) return;
    __threadfence();

    // ---- final: 1024 samples, 8 threads/sample, mirrors the bf16 product ----
    bool is64 = true;
    #pragma unroll
    for (int j = 1; j < 16; j += 2)
        if (ysw[j] != 0) is64 = false;               // int64 labels: odd words 0

    const int l8 = tid & 7, sg = tid >> 3;
    float lsum = 0.f;
    for (int k = 0; k < 32; ++k) {
        int s = k * 32 + sg;
        int y = is64 ? ysw[2 * s] : ysw[s];
        const float4* pv = reinterpret_cast<const float4*>(proxies + (size_t)y * DIM + l8 * 8);
        const float4* xv = reinterpret_cast<const float4*>(xs      + (size_t)s * DIM + l8 * 8);
        float4 p0 = pv[0], p1 = pv[1];
        float4 x0 = xv[0], x1 = xv[1];
        float ss = p0.x*p0.x + p0.y*p0.y + p0.z*p0.z + p0.w*p0.w
                 + p1.x*p1.x + p1.y*p1.y + p1.z*p1.z + p1.w*p1.w;
        ss += __shfl_xor_sync(0xffffffffu, ss, 1);
        ss += __shfl_xor_sync(0xffffffffu, ss, 2);
        ss += __shfl_xor_sync(0xffffffffu, ss, 4);
        float sc = (2.0f * LOG2E) / fmaxf(sqrtf(ss), 1e-12f);
        float pe[8] = {p0.x, p0.y, p0.z, p0.w, p1.x, p1.y, p1.z, p1.w};
        float xe[8] = {x0.x, x0.y, x0.z, x0.w, x1.x, x1.y, x1.z, x1.w};
        float dot = 0.f;
        #pragma unroll
        for (int e = 0; e < 8; ++e) {
            float pb = __bfloat162float(__float2bfloat16(pe[e] * sc));
            float xb = __bfloat162float(__float2bfloat16(xe[e]));
            dot += pb * xb;
        }
        dot += __shfl_xor_sync(0xffffffffu, dot, 1);
        dot += __shfl_xor_sync(0xffffffffu, dot, 2);
        dot += __shfl_xor_sync(0xffffffffu, dot, 4);
        if (l8 == 0) {
            float S = g_S[s] - (float)(CPAD - NB_C) * expf(-1.0f);  // remove pads
            float tpos = dot * LN2 - 1.0f;
            lsum += logf(S - ex2(dot - LOG2E)) - tpos;
        }
    }
    __shared__ float red[256];
    red[tid] = lsum;
    __syncthreads();
    for (int sft = 128; sft > 0; sft >>= 1) {
        if (tid < sft) red[tid] += red[tid + sft];
        __syncthreads();
    }
    if (tid == 0) out[0] = red[0] * (1.0f / 1024.0f);
}

// ---------------------------------------------------------------------------
// Launch: 2 kernels, graph-capturable.
// ---------------------------------------------------------------------------
extern "C" void kernel_launch(void* const* d_in, const int* in_sizes, int n_in,
                              void* d_out, int out_size) {
    const float* xs = nullptr; const int* ys = nullptr; const float* proxies = nullptr;
    for (int i = 0; i < n_in; ++i) {
        if      (in_sizes[i] == BATCH * DIM) xs      = (const float*)d_in[i];
        else if (in_sizes[i] == BATCH)       ys      = (const int*)d_in[i];
        else if (in_sizes[i] == NB_C * DIM)  proxies = (const float*)d_in[i];
    }
    (void)out_size;

    cudaFuncSetAttribute(gemm_kernel, cudaFuncAttributeMaxDynamicSharedMemorySize,
                         SMEM_BYTES);

    prep_kernel<<<K1_GRID, 256>>>(proxies, xs);
    gemm_kernel<<<GRID, 256, SMEM_BYTES>>>(proxies, xs, ys, (float*)d_out);
}